// round 11
// baseline (speedup 1.0000x reference)
#include <cuda_runtime.h>
#include <cuda_bf16.h>
#include <math.h>
#include <cstdint>

#define BATCH 2
#define NSEQ  2048
#define DIM   2048
#define NH    16
#define DH    128
#define INNER 2048
#define KDIM  2048
#define QK_SCALE 0.08838834764831845f  /* 128^-0.5 */

// ---------------------------------------------------------------------------
// Scratch
// ---------------------------------------------------------------------------
__device__ float g_qproj[BATCH * NSEQ * INNER];
__device__ float g_kv[BATCH * NSEQ * 2 * DH];
__device__ float g_attn[BATCH * NSEQ * INNER];
__device__ float g_WT[DIM * INNER];                 // transpose scratch (reused)
// int8 operand buffers (hi digit, lo digit) + per-row scales
__device__ int8_t g_x1[BATCH * NSEQ * DIM];
__device__ int8_t g_x0[BATCH * NSEQ * DIM];
__device__ float  g_sx[BATCH * NSEQ];
__device__ int8_t g_wq1[INNER * DIM];
__device__ int8_t g_wq0[INNER * DIM];
__device__ float  g_swq[INNER];
__device__ int8_t g_wkv1[2 * DH * DIM];
__device__ int8_t g_wkv0[2 * DH * DIM];
__device__ float  g_swkv[2 * DH];
__device__ int8_t g_wo1[DIM * INNER];
__device__ int8_t g_wo0[DIM * INNER];
__device__ float  g_swo[DIM];
__device__ int8_t g_at1[BATCH * NSEQ * INNER];
__device__ int8_t g_at0[BATCH * NSEQ * INNER];
__device__ float  g_sat[BATCH * NSEQ];

// ---------------------------------------------------------------------------
// PTX helpers
// ---------------------------------------------------------------------------
__device__ __forceinline__ uint32_t smem_u32(const void* p) {
    uint32_t a;
    asm("{ .reg .u64 t; cvta.to.shared.u64 t, %1; cvt.u32.u64 %0, t; }" : "=r"(a) : "l"(p));
    return a;
}
__device__ __forceinline__ void ldmat_x4(uint32_t* r, uint32_t addr) {
    asm volatile("ldmatrix.sync.aligned.m8n8.x4.shared.b16 {%0,%1,%2,%3}, [%4];"
                 : "=r"(r[0]), "=r"(r[1]), "=r"(r[2]), "=r"(r[3]) : "r"(addr));
}
__device__ __forceinline__ void ldmat_x4_t(uint32_t* r, uint32_t addr) {
    asm volatile("ldmatrix.sync.aligned.m8n8.x4.trans.shared.b16 {%0,%1,%2,%3}, [%4];"
                 : "=r"(r[0]), "=r"(r[1]), "=r"(r[2]), "=r"(r[3]) : "r"(addr));
}
__device__ __forceinline__ void mma_bf16(float* d, const uint32_t* a, const uint32_t* b) {
    asm("mma.sync.aligned.m16n8k16.row.col.f32.bf16.bf16.f32 "
        "{%0,%1,%2,%3}, {%4,%5,%6,%7}, {%8,%9}, {%0,%1,%2,%3};"
        : "+f"(d[0]), "+f"(d[1]), "+f"(d[2]), "+f"(d[3])
        : "r"(a[0]), "r"(a[1]), "r"(a[2]), "r"(a[3]), "r"(b[0]), "r"(b[1]));
}
// int8 MMA, K=32 per instruction, s32 accumulate
__device__ __forceinline__ void mma_s8(int* d, const uint32_t* a, const uint32_t* b) {
    asm("mma.sync.aligned.m16n8k32.row.col.s32.s8.s8.s32 "
        "{%0,%1,%2,%3}, {%4,%5,%6,%7}, {%8,%9}, {%0,%1,%2,%3};"
        : "+r"(d[0]), "+r"(d[1]), "+r"(d[2]), "+r"(d[3])
        : "r"(a[0]), "r"(a[1]), "r"(a[2]), "r"(a[3]), "r"(b[0]), "r"(b[1]));
}
__device__ __forceinline__ uint32_t pack_bf16x2(float x0, float x1) {
    uint32_t r;
    asm("cvt.rn.bf16x2.f32 %0, %1, %2;" : "=r"(r) : "f"(x1), "f"(x0));
    return r;
}
__device__ __forceinline__ void split_pair(float x0, float x1, uint32_t& hi, uint32_t& lo) {
    hi = pack_bf16x2(x0, x1);
    float h0 = __uint_as_float(hi << 16);
    float h1 = __uint_as_float(hi & 0xffff0000u);
    lo = pack_bf16x2(x0 - h0, x1 - h1);
}
__device__ __forceinline__ void cp16(uint32_t s, const void* g) {
    asm volatile("cp.async.cg.shared.global [%0], [%1], 16;" :: "r"(s), "l"(g));
}
#define CP_COMMIT() asm volatile("cp.async.commit_group;" ::: "memory")
#define CP_WAIT0()  asm volatile("cp.async.wait_group 0;" ::: "memory")

// ---------------------------------------------------------------------------
// Weight transpose: in [R, C] -> out [C, R]  (fp32)
// ---------------------------------------------------------------------------
__global__ void transpose_kernel(const float* __restrict__ in, float* __restrict__ out,
                                 int R, int C)
{
    __shared__ float t[32][33];
    int c0 = blockIdx.x << 5, r0 = blockIdx.y << 5;
    int x = threadIdx.x, y = threadIdx.y;
#pragma unroll
    for (int i = 0; i < 32; i += 8)
        t[y + i][x] = in[(size_t)(r0 + y + i) * C + c0 + x];
    __syncthreads();
#pragma unroll
    for (int i = 0; i < 32; i += 8)
        out[(size_t)(c0 + y + i) * R + r0 + x] = t[x][y + i];
}

// ---------------------------------------------------------------------------
// Row quantization: fp32 [rows, 2048] -> 16-bit fixed point as two int8 digits
// x = s*(a1*256 + a0), s = rowmax/32639.  One block per row, 256 threads.
// ---------------------------------------------------------------------------
__global__ __launch_bounds__(256) void quant_rows(
    const float* __restrict__ in, int8_t* __restrict__ o1,
    int8_t* __restrict__ o0, float* __restrict__ sc)
{
    __shared__ float red[256];
    const int tid = threadIdx.x;
    const size_t row = blockIdx.x;
    const float* rp = in + row * 2048;

    float v[8];
    float mx = 0.f;
#pragma unroll
    for (int i = 0; i < 8; i++) {
        v[i] = rp[tid + (i << 8)];
        mx = fmaxf(mx, fabsf(v[i]));
    }
    red[tid] = mx;
    __syncthreads();
    for (int o = 128; o > 0; o >>= 1) {
        if (tid < o) red[tid] = fmaxf(red[tid], red[tid + o]);
        __syncthreads();
    }
    float m = red[0];
    float inv = (m > 0.f) ? 32639.f / m : 0.f;
    float s = (m > 0.f) ? m * (1.f / 32639.f) : 1.f;
#pragma unroll
    for (int i = 0; i < 8; i++) {
        int q = __float2int_rn(v[i] * inv);
        q = max(-32639, min(32639, q));
        int a1 = (q + 128) >> 8;
        int a0 = q - (a1 << 8);
        size_t idx = row * 2048 + tid + (i << 8);
        o1[idx] = (int8_t)a1;
        o0[idx] = (int8_t)a0;
    }
    if (tid == 0) sc[row] = s;
}

// ---------------------------------------------------------------------------
// int8 split GEMM: C[M,N] = sA sB * ((A1*256+A0) @ (B1*256+B0)^T), drop A0B0.
// 128x128 CTA tile, BK=64 (2 x k32 steps), 8 warps, 32x64 warp tiles.
// 3 MMA passes/step: a1b1 -> acc_hi; a1b0, a0b1 -> acc_mid (same 2^8 scale).
// SMEM: 4 buffers (A1 A0 B1 B0) x 128 rows x 64B, pitch 80 -> conflict-free.
// Staging is pure cp.async copies (operands pre-quantized).
// ---------------------------------------------------------------------------
#define GP8 80
#define G8BUF (128 * GP8)            /* 10240 */
#define G8STAGE (4 * G8BUF)          /* 40960 */
#define GEMM8_SMEM (2 * G8STAGE)     /* 81920 */
#define NKIT8 (KDIM / 64)            /* 32 */

extern __shared__ float fsm[];

__global__ __launch_bounds__(256, 1) void gemm_i8(
    const int8_t* __restrict__ A1, const int8_t* __restrict__ A0,
    const float* __restrict__ sA,
    const int8_t* __restrict__ B1, const int8_t* __restrict__ B0,
    const float* __restrict__ sB,
    float* __restrict__ C, int M, int N)
{
    char* sm = (char*)fsm;
    const uint32_t smb = smem_u32(sm);
    const int tid = threadIdx.x;
    const int wid = tid >> 5, L = tid & 31;
    const int wm = wid & 3, wn = wid >> 2;
    const int m0 = blockIdx.y << 7, n0 = blockIdx.x << 7;

    int acc_hi[2][8][4], acc_mid[2][8][4];
#pragma unroll
    for (int mi = 0; mi < 2; mi++)
#pragma unroll
        for (int ni = 0; ni < 8; ni++)
#pragma unroll
            for (int e = 0; e < 4; e++) { acc_hi[mi][ni][e] = 0; acc_mid[mi][ni][e] = 0; }

    auto issue = [&](int kc, int stg) {
        uint32_t sb = smb + (uint32_t)stg * G8STAGE;
        int kb = kc << 6;                        // 64 bytes per chunk along K
#pragma unroll
        for (int i = 0; i < 2; i++) {
            int idx = tid + (i << 8);            // 0..511
            int row = idx >> 2, c16 = (idx & 3) << 4;
            uint32_t so = sb + (uint32_t)row * GP8 + c16;
            size_t ga = (size_t)(m0 + row) * KDIM + kb + c16;
            size_t gb = (size_t)(n0 + row) * KDIM + kb + c16;
            cp16(so,             (const char*)A1 + ga);
            cp16(so + G8BUF,     (const char*)A0 + ga);
            cp16(so + 2 * G8BUF, (const char*)B1 + gb);
            cp16(so + 3 * G8BUF, (const char*)B0 + gb);
        }
    };

    const uint32_t a_row_off = (uint32_t)(wm * 32 + (L & 15)) * GP8 + ((L >> 4) << 4);
    const uint32_t b_row_off = (uint32_t)(wn * 64 + ((L >> 4) << 3) + (L & 7)) * GP8
                               + (((L >> 3) & 1) << 4);

    auto compute = [&](int stg) {
        const uint32_t base = smb + (uint32_t)stg * G8STAGE;
#pragma unroll
        for (int ks = 0; ks < 2; ks++) {
            const uint32_t kso = (uint32_t)(ks << 5);     // 32 bytes per k32 step
            uint32_t a1f[2][4], a0f[2][4], b1f[8][2], b0f[8][2];
#pragma unroll
            for (int mi = 0; mi < 2; mi++) {
                uint32_t ad = base + a_row_off + (uint32_t)(mi * 16) * GP8 + kso;
                ldmat_x4(a1f[mi], ad);
                ldmat_x4(a0f[mi], ad + G8BUF);
            }
#pragma unroll
            for (int nj = 0; nj < 4; nj++) {
                uint32_t bd = base + 2 * G8BUF + b_row_off
                              + (uint32_t)(nj * 16) * GP8 + kso;
                uint32_t r4[4];
                ldmat_x4(r4, bd);
                b1f[2 * nj][0] = r4[0]; b1f[2 * nj][1] = r4[1];
                b1f[2 * nj + 1][0] = r4[2]; b1f[2 * nj + 1][1] = r4[3];
                ldmat_x4(r4, bd + G8BUF);
                b0f[2 * nj][0] = r4[0]; b0f[2 * nj][1] = r4[1];
                b0f[2 * nj + 1][0] = r4[2]; b0f[2 * nj + 1][1] = r4[3];
            }
#pragma unroll
            for (int mi = 0; mi < 2; mi++)
#pragma unroll
                for (int ni = 0; ni < 8; ni++)
                    mma_s8(acc_hi[mi][ni], a1f[mi], b1f[ni]);
#pragma unroll
            for (int mi = 0; mi < 2; mi++)
#pragma unroll
                for (int ni = 0; ni < 8; ni++)
                    mma_s8(acc_mid[mi][ni], a1f[mi], b0f[ni]);
#pragma unroll
            for (int mi = 0; mi < 2; mi++)
#pragma unroll
                for (int ni = 0; ni < 8; ni++)
                    mma_s8(acc_mid[mi][ni], a0f[mi], b1f[ni]);
        }
    };

    issue(0, 0);
    CP_COMMIT();
#pragma unroll 1
    for (int kc = 0; kc < NKIT8; kc++) {
        CP_WAIT0();
        __syncthreads();
        if (kc + 1 < NKIT8) { issue(kc + 1, (kc + 1) & 1); CP_COMMIT(); }
        compute(kc & 1);
        if (kc + 1 < NKIT8) __syncthreads();  // compute done before next overwrite cycle
    }

    // Epilogue: C = sA*sB*(65536*hi + 256*mid)
#pragma unroll
    for (int mi = 0; mi < 2; mi++) {
        int row = m0 + wm * 32 + mi * 16 + (L >> 2);
        float sa0 = sA[row], sa1 = sA[row + 8];
#pragma unroll
        for (int ni = 0; ni < 8; ni++) {
            int col = n0 + wn * 64 + ni * 8 + ((L & 3) << 1);
            float sb0 = sB[col], sb1 = sB[col + 1];
            float c00 = sa0 * sb0 * (65536.f * (float)acc_hi[mi][ni][0] + 256.f * (float)acc_mid[mi][ni][0]);
            float c01 = sa0 * sb1 * (65536.f * (float)acc_hi[mi][ni][1] + 256.f * (float)acc_mid[mi][ni][1]);
            float c10 = sa1 * sb0 * (65536.f * (float)acc_hi[mi][ni][2] + 256.f * (float)acc_mid[mi][ni][2]);
            float c11 = sa1 * sb1 * (65536.f * (float)acc_hi[mi][ni][3] + 256.f * (float)acc_mid[mi][ni][3]);
            *(float2*)&C[(size_t)row * N + col]       = make_float2(c00, c01);
            *(float2*)&C[(size_t)(row + 8) * N + col] = make_float2(c10, c11);
        }
    }
}

// ---------------------------------------------------------------------------
// RoPE (in place): q heads rotated + scaled by 1/sqrt(d); k rotated.
// ---------------------------------------------------------------------------
__global__ void rope_kernel()
{
    int t = blockIdx.x * blockDim.x + threadIdx.x;
    const int TOT = BATCH * NSEQ * 17 * 64;
    if (t >= TOT) return;
    int pair = t & 63;
    int unit = (t >> 6) % 17;
    int rest = t / (64 * 17);
    int n = rest % NSEQ;
    int b = rest / NSEQ;

    float invf = powf(10000.f, -(float)(pair << 1) * (1.f / 128.f));
    float ang = (float)n * invf;
    float s, c;
    sincosf(ang, &s, &c);

    float* base;
    float sc;
    if (unit < NH) {
        base = g_qproj + ((size_t)(b * NSEQ + n)) * INNER + unit * DH;
        sc = QK_SCALE;
    } else {
        base = g_kv + ((size_t)(b * NSEQ + n)) * (2 * DH);
        sc = 1.f;
    }
    float x1 = base[pair], x2 = base[pair + 64];
    base[pair]      = (x1 * c - x2 * s) * sc;
    base[pair + 64] = (x2 * c + x1 * s) * sc;
}

// ---------------------------------------------------------------------------
// Flash attention with split-bf16 mma (identical to R7 best).
// ---------------------------------------------------------------------------
#define FB_PITCH 272
#define FB_SIZE (128 * FB_PITCH)
#define FLASH_SMEM (6 * FB_SIZE)

__global__ __launch_bounds__(256, 1) void flash_mma()
{
    char* sm = (char*)fsm;
    const uint32_t smb = smem_u32(sm);
    const int tid = threadIdx.x;
    const int wid = tid >> 5, L = tid & 31;
    const int ib = blockIdx.x, h = blockIdx.y, b = blockIdx.z;
    const int r0 = ib << 7;
    const int wr0 = wid << 4;

    const float* qg  = g_qproj + (size_t)b * NSEQ * INNER + h * DH;
    const float* kvg = g_kv + (size_t)b * NSEQ * (2 * DH);

#pragma unroll
    for (int t = 0; t < 16; t++) {
        int idx = tid + (t << 8);
        int r = idx >> 5, c4 = idx & 31;
        float4 v = *(const float4*)&qg[(size_t)(r0 + r) * INNER + (c4 << 2)];
        uint32_t h0, l0, h1, l1;
        split_pair(v.x, v.y, h0, l0);
        split_pair(v.z, v.w, h1, l1);
        uint32_t off = (uint32_t)r * FB_PITCH + (c4 << 3);
        *(uint2*)(sm + off)           = make_uint2(h0, h1);
        *(uint2*)(sm + FB_SIZE + off) = make_uint2(l0, l1);
    }

    const uint32_t aoff = (uint32_t)(wr0 + (L & 15)) * FB_PITCH + ((L >> 4) << 4);
    const uint32_t koff = (uint32_t)(((L >> 4) << 3) + (L & 7)) * FB_PITCH
                          + (((L >> 3) & 1) << 4);
    const uint32_t voff = (uint32_t)((((L >> 3) & 1) << 3) + (L & 7)) * FB_PITCH
                          + ((L >> 4) << 4);

    float sO[16][4];
    float m_i[2], l_i[2];
#pragma unroll
    for (int nj = 0; nj < 16; nj++)
#pragma unroll
        for (int e = 0; e < 4; e++) sO[nj][e] = 0.f;
    m_i[0] = m_i[1] = -INFINITY;
    l_i[0] = l_i[1] = 0.f;

#pragma unroll 1
    for (int jb = 0; jb <= ib; jb++) {
        __syncthreads();
        const int c0 = jb << 7;
#pragma unroll
        for (int t = 0; t < 16; t++) {
            int idx = tid + (t << 8);
            int r = idx >> 5, c4 = idx & 31;
            const float4* row = (const float4*)&kvg[(size_t)(c0 + r) * 256];
            uint32_t off = (uint32_t)r * FB_PITCH + (c4 << 3);
            float4 kv4 = row[c4];
            uint32_t h0, l0, h1, l1;
            split_pair(kv4.x, kv4.y, h0, l0);
            split_pair(kv4.z, kv4.w, h1, l1);
            *(uint2*)(sm + 2 * FB_SIZE + off) = make_uint2(h0, h1);
            *(uint2*)(sm + 3 * FB_SIZE + off) = make_uint2(l0, l1);
            float4 vv4 = row[32 + c4];
            split_pair(vv4.x, vv4.y, h0, l0);
            split_pair(vv4.z, vv4.w, h1, l1);
            *(uint2*)(sm + 4 * FB_SIZE + off) = make_uint2(h0, h1);
            *(uint2*)(sm + 5 * FB_SIZE + off) = make_uint2(l0, l1);
        }
        __syncthreads();

        float s[16][4];
#pragma unroll
        for (int nj = 0; nj < 16; nj++)
#pragma unroll
            for (int e = 0; e < 4; e++) s[nj][e] = 0.f;
#pragma unroll
        for (int ks = 0; ks < 8; ks++) {
            const uint32_t kso = (uint32_t)(ks << 5);
            uint32_t ah[4], al[4];
            ldmat_x4(ah, smb + aoff + kso);
            ldmat_x4(al, smb + FB_SIZE + aoff + kso);
#pragma unroll
            for (int g = 0; g < 2; g++) {
                uint32_t bh[8][2], bl[8][2];
#pragma unroll
                for (int jj = 0; jj < 4; jj++) {
                    int njp = g * 4 + jj;
                    uint32_t kd = smb + 2 * FB_SIZE + koff
                                  + (uint32_t)(njp * 16) * FB_PITCH + kso;
                    uint32_t r4[4];
                    ldmat_x4(r4, kd);
                    bh[2 * jj][0] = r4[0]; bh[2 * jj][1] = r4[1];
                    bh[2 * jj + 1][0] = r4[2]; bh[2 * jj + 1][1] = r4[3];
                    ldmat_x4(r4, kd + FB_SIZE);
                    bl[2 * jj][0] = r4[0]; bl[2 * jj][1] = r4[1];
                    bl[2 * jj + 1][0] = r4[2]; bl[2 * jj + 1][1] = r4[3];
                }
#pragma unroll
                for (int t = 0; t < 8; t++) mma_bf16(s[8 * g + t], ah, bh[t]);
#pragma unroll
                for (int t = 0; t < 8; t++) mma_bf16(s[8 * g + t], ah, bl[t]);
#pragma unroll
                for (int t = 0; t < 8; t++) mma_bf16(s[8 * g + t], al, bh[t]);
            }
        }

        if (jb == ib) {
            int rr = L >> 2, cb = (L & 3) << 1;
#pragma unroll
            for (int nj = 0; nj < 16; nj++) {
                int col = nj * 8 + cb;
                int rA = wr0 + rr, rB = rA + 8;
                if (col     > rA) s[nj][0] = -1e30f;
                if (col + 1 > rA) s[nj][1] = -1e30f;
                if (col     > rB) s[nj][2] = -1e30f;
                if (col + 1 > rB) s[nj][3] = -1e30f;
            }
        }

#pragma unroll
        for (int h2 = 0; h2 < 2; h2++) {
            float mx = -INFINITY;
#pragma unroll
            for (int nj = 0; nj < 16; nj++) {
                mx = fmaxf(mx, s[nj][2 * h2]);
                mx = fmaxf(mx, s[nj][2 * h2 + 1]);
            }
            mx = fmaxf(mx, __shfl_xor_sync(0xffffffffu, mx, 1));
            mx = fmaxf(mx, __shfl_xor_sync(0xffffffffu, mx, 2));
            float mn = fmaxf(m_i[h2], mx);
            float alpha = __expf(m_i[h2] - mn);
            m_i[h2] = mn;
            float sum = 0.f;
#pragma unroll
            for (int nj = 0; nj < 16; nj++) {
                float p0 = __expf(s[nj][2 * h2] - mn);
                float p1 = __expf(s[nj][2 * h2 + 1] - mn);
                s[nj][2 * h2] = p0;
                s[nj][2 * h2 + 1] = p1;
                sum += p0 + p1;
            }
            sum += __shfl_xor_sync(0xffffffffu, sum, 1);
            sum += __shfl_xor_sync(0xffffffffu, sum, 2);
            l_i[h2] = l_i[h2] * alpha + sum;
#pragma unroll
            for (int nj = 0; nj < 16; nj++) {
                sO[nj][2 * h2] *= alpha;
                sO[nj][2 * h2 + 1] *= alpha;
            }
        }

#pragma unroll
        for (int ks = 0; ks < 8; ks++) {
            uint32_t pah[4], pal[4];
            split_pair(s[2 * ks][0], s[2 * ks][1], pah[0], pal[0]);
            split_pair(s[2 * ks][2], s[2 * ks][3], pah[1], pal[1]);
            split_pair(s[2 * ks + 1][0], s[2 * ks + 1][1], pah[2], pal[2]);
            split_pair(s[2 * ks + 1][2], s[2 * ks + 1][3], pah[3], pal[3]);
#pragma unroll
            for (int g = 0; g < 2; g++) {
                uint32_t vh[8][2], vl[8][2];
#pragma unroll
                for (int jj = 0; jj < 4; jj++) {
                    int djp = g * 4 + jj;
                    uint32_t vaddr = smb + 4 * FB_SIZE + voff
                                     + (uint32_t)(ks * 16) * FB_PITCH
                                     + (uint32_t)(djp * 32);
                    uint32_t r4[4];
                    ldmat_x4_t(r4, vaddr);
                    vh[2 * jj][0] = r4[0]; vh[2 * jj][1] = r4[1];
                    vh[2 * jj + 1][0] = r4[2]; vh[2 * jj + 1][1] = r4[3];
                    ldmat_x4_t(r4, vaddr + FB_SIZE);
                    vl[2 * jj][0] = r4[0]; vl[2 * jj][1] = r4[1];
                    vl[2 * jj + 1][0] = r4[2]; vl[2 * jj + 1][1] = r4[3];
                }
#pragma unroll
                for (int t = 0; t < 8; t++) mma_bf16(sO[8 * g + t], pah, vh[t]);
#pragma unroll
                for (int t = 0; t < 8; t++) mma_bf16(sO[8 * g + t], pal, vh[t]);
#pragma unroll
                for (int t = 0; t < 8; t++) mma_bf16(sO[8 * g + t], pah, vl[t]);
            }
        }
    }

    float* og = g_attn + (size_t)b * NSEQ * INNER + h * DH;
    int rowa = r0 + wr0 + (L >> 2);
#pragma unroll
    for (int h2 = 0; h2 < 2; h2++) {
        float inv = 1.f / l_i[h2];
        float* orow = &og[(size_t)(rowa + 8 * h2) * INNER];
#pragma unroll
        for (int nj = 0; nj < 16; nj++) {
            int col = nj * 8 + ((L & 3) << 1);
            *(float2*)&orow[col] =
                make_float2(sO[nj][2 * h2] * inv, sO[nj][2 * h2 + 1] * inv);
        }
    }
}

// ---------------------------------------------------------------------------
extern "C" void kernel_launch(void* const* d_in, const int* in_sizes, int n_in,
                              void* d_out, int out_size)
{
    (void)in_sizes; (void)n_in; (void)out_size;
    const float* x    = (const float*)d_in[0];
    const float* Wq   = (const float*)d_in[1];
    const float* Wkv  = (const float*)d_in[2];
    const float* Wout = (const float*)d_in[3];
    float* out = (float*)d_out;

    void *pq, *pkv, *pattn, *pwt;
    void *px1, *px0, *psx, *pwq1, *pwq0, *pswq, *pwk1, *pwk0, *pswk;
    void *pwo1, *pwo0, *pswo, *pat1, *pat0, *psat;
    cudaGetSymbolAddress(&pq, g_qproj);
    cudaGetSymbolAddress(&pkv, g_kv);
    cudaGetSymbolAddress(&pattn, g_attn);
    cudaGetSymbolAddress(&pwt, g_WT);
    cudaGetSymbolAddress(&px1, g_x1);   cudaGetSymbolAddress(&px0, g_x0);
    cudaGetSymbolAddress(&psx, g_sx);
    cudaGetSymbolAddress(&pwq1, g_wq1); cudaGetSymbolAddress(&pwq0, g_wq0);
    cudaGetSymbolAddress(&pswq, g_swq);
    cudaGetSymbolAddress(&pwk1, g_wkv1); cudaGetSymbolAddress(&pwk0, g_wkv0);
    cudaGetSymbolAddress(&pswk, g_swkv);
    cudaGetSymbolAddress(&pwo1, g_wo1); cudaGetSymbolAddress(&pwo0, g_wo0);
    cudaGetSymbolAddress(&pswo, g_swo);
    cudaGetSymbolAddress(&pat1, g_at1); cudaGetSymbolAddress(&pat0, g_at0);
    cudaGetSymbolAddress(&psat, g_sat);

    cudaFuncSetAttribute(gemm_i8,
                         cudaFuncAttributeMaxDynamicSharedMemorySize, GEMM8_SMEM);
    cudaFuncSetAttribute(flash_mma,
                         cudaFuncAttributeMaxDynamicSharedMemorySize, FLASH_SMEM);

    const int M = BATCH * NSEQ;  // 4096
    dim3 tb(32, 8);

    // 0) quantize x; transpose+quantize weights (WT scratch reused sequentially)
    quant_rows<<<M, 256>>>(x, (int8_t*)px1, (int8_t*)px0, (float*)psx);
    transpose_kernel<<<dim3(INNER / 32, DIM / 32), tb>>>(Wq, (float*)pwt, DIM, INNER);
    quant_rows<<<INNER, 256>>>((const float*)pwt, (int8_t*)pwq1, (int8_t*)pwq0, (float*)pswq);
    transpose_kernel<<<dim3((2 * DH) / 32, DIM / 32), tb>>>(Wkv, (float*)pwt, DIM, 2 * DH);
    quant_rows<<<2 * DH, 256>>>((const float*)pwt, (int8_t*)pwk1, (int8_t*)pwk0, (float*)pswk);
    transpose_kernel<<<dim3(DIM / 32, INNER / 32), tb>>>(Wout, (float*)pwt, INNER, DIM);
    quant_rows<<<DIM, 256>>>((const float*)pwt, (int8_t*)pwo1, (int8_t*)pwo0, (float*)pswo);

    // 1) q = x @ Wq
    gemm_i8<<<dim3(INNER / 128, M / 128), 256, GEMM8_SMEM>>>(
        (const int8_t*)px1, (const int8_t*)px0, (const float*)psx,
        (const int8_t*)pwq1, (const int8_t*)pwq0, (const float*)pswq,
        (float*)pq, M, INNER);
    // 2) kv = x @ Wkv
    gemm_i8<<<dim3((2 * DH) / 128, M / 128), 256, GEMM8_SMEM>>>(
        (const int8_t*)px1, (const int8_t*)px0, (const float*)psx,
        (const int8_t*)pwk1, (const int8_t*)pwk0, (const float*)pswk,
        (float*)pkv, M, 2 * DH);
    // 3) RoPE in place (+ q scaling)
    {
        int tot = BATCH * NSEQ * 17 * 64;
        rope_kernel<<<(tot + 255) / 256, 256>>>();
    }
    // 4) causal flash attention (split-bf16 mma)
    flash_mma<<<dim3(NSEQ / 128, NH, BATCH), 256, FLASH_SMEM>>>();
    // 5) quantize attention output, then out = attn @ Wout
    quant_rows<<<M, 256>>>((const float*)pattn, (int8_t*)pat1, (int8_t*)pat0, (float*)psat);
    gemm_i8<<<dim3(DIM / 128, M / 128), 256, GEMM8_SMEM>>>(
        (const int8_t*)pat1, (const int8_t*)pat0, (const float*)psat,
        (const int8_t*)pwo1, (const int8_t*)pwo0, (const float*)pswo,
        out, M, DIM);
}

// round 13
// speedup vs baseline: 2.3211x; 2.3211x over previous
#include <cuda_runtime.h>
#include <cuda_bf16.h>
#include <math.h>
#include <cstdint>

#define BATCH 2
#define NSEQ  2048
#define DIM   2048
#define NH    16
#define DH    128
#define INNER 2048
#define KDIM  2048
#define QK_SCALE 0.08838834764831845f  /* 128^-0.5 */

// ---------------------------------------------------------------------------
// Scratch
// ---------------------------------------------------------------------------
__device__ float g_qproj[BATCH * NSEQ * INNER];
__device__ float g_kv[BATCH * NSEQ * 2 * DH];
__device__ float g_attn[BATCH * NSEQ * INNER];
__device__ float g_WT[(INNER + 2 * DH) * DIM];   // [Wq^T ; Wkv^T] 2304 x 2048
__device__ float g_WoutT[DIM * INNER];

__device__ __forceinline__ uint32_t smem_u32(const void* p) {
    uint32_t a;
    asm("{ .reg .u64 t; cvta.to.shared.u64 t, %1; cvt.u32.u64 %0, t; }" : "=r"(a) : "l"(p));
    return a;
}
__device__ __forceinline__ void ldmat_x4(uint32_t* r, uint32_t addr) {
    asm volatile("ldmatrix.sync.aligned.m8n8.x4.shared.b16 {%0,%1,%2,%3}, [%4];"
                 : "=r"(r[0]), "=r"(r[1]), "=r"(r[2]), "=r"(r[3]) : "r"(addr));
}
__device__ __forceinline__ void ldmat_x4_t(uint32_t* r, uint32_t addr) {
    asm volatile("ldmatrix.sync.aligned.m8n8.x4.trans.shared.b16 {%0,%1,%2,%3}, [%4];"
                 : "=r"(r[0]), "=r"(r[1]), "=r"(r[2]), "=r"(r[3]) : "r"(addr));
}
__device__ __forceinline__ void mma_bf16(float* d, const uint32_t* a, const uint32_t* b) {
    asm("mma.sync.aligned.m16n8k16.row.col.f32.bf16.bf16.f32 "
        "{%0,%1,%2,%3}, {%4,%5,%6,%7}, {%8,%9}, {%0,%1,%2,%3};"
        : "+f"(d[0]), "+f"(d[1]), "+f"(d[2]), "+f"(d[3])
        : "r"(a[0]), "r"(a[1]), "r"(a[2]), "r"(a[3]), "r"(b[0]), "r"(b[1]));
}
__device__ __forceinline__ uint32_t pack_bf16x2(float x0, float x1) {
    uint32_t r;
    asm("cvt.rn.bf16x2.f32 %0, %1, %2;" : "=r"(r) : "f"(x1), "f"(x0));
    return r;
}
__device__ __forceinline__ void split_pair(float x0, float x1, uint32_t& hi, uint32_t& lo) {
    hi = pack_bf16x2(x0, x1);
    float h0 = __uint_as_float(hi << 16);
    float h1 = __uint_as_float(hi & 0xffff0000u);
    lo = pack_bf16x2(x0 - h0, x1 - h1);
}

// ---------------------------------------------------------------------------
// Weight transpose: in [R, C] -> out [C, R]
// ---------------------------------------------------------------------------
__global__ void transpose_kernel(const float* __restrict__ in, float* __restrict__ out,
                                 int R, int C)
{
    __shared__ float t[32][33];
    int c0 = blockIdx.x << 5, r0 = blockIdx.y << 5;
    int x = threadIdx.x, y = threadIdx.y;
#pragma unroll
    for (int i = 0; i < 32; i += 8)
        t[y + i][x] = in[(size_t)(r0 + y + i) * C + c0 + x];
    __syncthreads();
#pragma unroll
    for (int i = 0; i < 32; i += 8)
        out[(size_t)(c0 + y + i) * R + r0 + x] = t[x][y + i];
}

// ---------------------------------------------------------------------------
// Split-bf16 mma.sync GEMM (R7 structure): computes
//   [C1 | C2] [M, *] = A[M,2048] @ BT[*,2048]^T
// CTA column tiles with n0 < N1 write to C1 (row stride N1); tiles with
// n0 >= N1 write to C2 (row stride N2) at column n0-N1. Tiles never straddle
// the boundary (N1 % 128 == 0).
// ---------------------------------------------------------------------------
#define PITCHB 80
#define BUF_BYTES (128 * PITCHB)
#define STAGE_BYTES (4 * BUF_BYTES)
#define GEMM_SMEM (2 * STAGE_BYTES)
#define NKIT (KDIM / 32)

extern __shared__ float fsm[];

__global__ __launch_bounds__(256, 1) void gemm_mma(
    const float* __restrict__ A, const float* __restrict__ BT,
    float* __restrict__ C1, float* __restrict__ C2,
    int M, int N1, int N2)
{
    char* sm = (char*)fsm;
    const uint32_t smb = smem_u32(sm);
    const int tid = threadIdx.x;
    const int wid = tid >> 5, L = tid & 31;
    const int wm = wid & 3, wn = wid >> 2;
    const int m0 = blockIdx.y << 7, n0 = blockIdx.x << 7;

    const int ldr = tid >> 3;
    const int ldc = tid & 7;

    float acc[2][8][4];
#pragma unroll
    for (int mi = 0; mi < 2; mi++)
#pragma unroll
        for (int ni = 0; ni < 8; ni++)
#pragma unroll
            for (int e = 0; e < 4; e++) acc[mi][ni][e] = 0.f;

    float4 va[4], vb[4];

    auto ldg_stage = [&](int kc) {
#pragma unroll
        for (int t = 0; t < 4; t++) {
            int r = ldr + (t << 5);
            va[t] = *(const float4*)&A[(size_t)(m0 + r) * KDIM + (kc << 5) + (ldc << 2)];
            vb[t] = *(const float4*)&BT[(size_t)(n0 + r) * KDIM + (kc << 5) + (ldc << 2)];
        }
    };
    auto sts_stage = [&](int stg) {
        char* base = sm + stg * STAGE_BYTES;
#pragma unroll
        for (int t = 0; t < 4; t++) {
            int r = ldr + (t << 5);
            uint32_t off = (uint32_t)r * PITCHB + (ldc << 3);
            uint32_t h0, l0, h1, l1;
            split_pair(va[t].x, va[t].y, h0, l0);
            split_pair(va[t].z, va[t].w, h1, l1);
            *(uint2*)(base + off)                 = make_uint2(h0, h1);
            *(uint2*)(base + BUF_BYTES + off)     = make_uint2(l0, l1);
            split_pair(vb[t].x, vb[t].y, h0, l0);
            split_pair(vb[t].z, vb[t].w, h1, l1);
            *(uint2*)(base + 2 * BUF_BYTES + off) = make_uint2(h0, h1);
            *(uint2*)(base + 3 * BUF_BYTES + off) = make_uint2(l0, l1);
        }
    };

    const uint32_t a_row_off = (uint32_t)(wm * 32 + (L & 15)) * PITCHB + ((L >> 4) << 4);
    const uint32_t b_row_off = (uint32_t)(wn * 64 + ((L >> 4) << 3) + (L & 7)) * PITCHB
                               + (((L >> 3) & 1) << 4);

    auto compute_stage = [&](int stg) {
        const uint32_t base = smb + stg * STAGE_BYTES;
#pragma unroll
        for (int ks = 0; ks < 2; ks++) {
            const uint32_t kso = (uint32_t)(ks << 5);
            uint32_t ah[2][4], al[2][4], bh[8][2], bl[8][2];
#pragma unroll
            for (int mi = 0; mi < 2; mi++) {
                uint32_t ad = base + a_row_off + (uint32_t)(mi * 16) * PITCHB + kso;
                ldmat_x4(ah[mi], ad);
                ldmat_x4(al[mi], ad + BUF_BYTES);
            }
#pragma unroll
            for (int nj = 0; nj < 4; nj++) {
                uint32_t bd = base + 2 * BUF_BYTES + b_row_off
                              + (uint32_t)(nj * 16) * PITCHB + kso;
                uint32_t r4[4];
                ldmat_x4(r4, bd);
                bh[2 * nj][0] = r4[0]; bh[2 * nj][1] = r4[1];
                bh[2 * nj + 1][0] = r4[2]; bh[2 * nj + 1][1] = r4[3];
                ldmat_x4(r4, bd + BUF_BYTES);
                bl[2 * nj][0] = r4[0]; bl[2 * nj][1] = r4[1];
                bl[2 * nj + 1][0] = r4[2]; bl[2 * nj + 1][1] = r4[3];
            }
#pragma unroll
            for (int mi = 0; mi < 2; mi++)
#pragma unroll
                for (int ni = 0; ni < 8; ni++)
                    mma_bf16(acc[mi][ni], ah[mi], bh[ni]);
#pragma unroll
            for (int mi = 0; mi < 2; mi++)
#pragma unroll
                for (int ni = 0; ni < 8; ni++)
                    mma_bf16(acc[mi][ni], ah[mi], bl[ni]);
#pragma unroll
            for (int mi = 0; mi < 2; mi++)
#pragma unroll
                for (int ni = 0; ni < 8; ni++)
                    mma_bf16(acc[mi][ni], al[mi], bh[ni]);
        }
    };

    ldg_stage(0);
    sts_stage(0);
    __syncthreads();
#pragma unroll 1
    for (int kc = 0; kc < NKIT; kc++) {
        if (kc + 1 < NKIT) ldg_stage(kc + 1);
        compute_stage(kc & 1);
        if (kc + 1 < NKIT) sts_stage((kc + 1) & 1);
        __syncthreads();
    }

    // Epilogue: route to C1 or C2 (whole CTA is on one side)
    float* Cb;
    int cstride, cb0;
    if (n0 < N1) { Cb = C1; cstride = N1; cb0 = n0; }
    else         { Cb = C2; cstride = N2; cb0 = n0 - N1; }
#pragma unroll
    for (int mi = 0; mi < 2; mi++) {
        int row = m0 + wm * 32 + mi * 16 + (L >> 2);
#pragma unroll
        for (int ni = 0; ni < 8; ni++) {
            int col = cb0 + wn * 64 + ni * 8 + ((L & 3) << 1);
            *(float2*)&Cb[(size_t)row * cstride + col] =
                make_float2(acc[mi][ni][0], acc[mi][ni][1]);
            *(float2*)&Cb[(size_t)(row + 8) * cstride + col] =
                make_float2(acc[mi][ni][2], acc[mi][ni][3]);
        }
    }
}

// ---------------------------------------------------------------------------
// RoPE (in place): q heads rotated + scaled by 1/sqrt(d); k rotated.
// ---------------------------------------------------------------------------
__global__ void rope_kernel()
{
    int t = blockIdx.x * blockDim.x + threadIdx.x;
    const int TOT = BATCH * NSEQ * 17 * 64;
    if (t >= TOT) return;
    int pair = t & 63;
    int unit = (t >> 6) % 17;
    int rest = t / (64 * 17);
    int n = rest % NSEQ;
    int b = rest / NSEQ;

    float invf = powf(10000.f, -(float)(pair << 1) * (1.f / 128.f));
    float ang = (float)n * invf;
    float s, c;
    sincosf(ang, &s, &c);

    float* base;
    float sc;
    if (unit < NH) {
        base = g_qproj + ((size_t)(b * NSEQ + n)) * INNER + unit * DH;
        sc = QK_SCALE;
    } else {
        base = g_kv + ((size_t)(b * NSEQ + n)) * (2 * DH);
        sc = 1.f;
    }
    float x1 = base[pair], x2 = base[pair + 64];
    base[pair]      = (x1 * c - x2 * s) * sc;
    base[pair + 64] = (x2 * c + x1 * s) * sc;
}

// ---------------------------------------------------------------------------
// Flash attention with split-bf16 mma (R7 math), HEAVIEST-FIRST block order:
// ib = 15 - blockIdx.x so long (16-tile) CTAs are scheduled first and short
// CTAs backfill -> balanced makespan instead of a heavy tail.
// ---------------------------------------------------------------------------
#define FB_PITCH 272
#define FB_SIZE (128 * FB_PITCH)
#define FLASH_SMEM (6 * FB_SIZE)

__global__ __launch_bounds__(256, 1) void flash_mma()
{
    char* sm = (char*)fsm;
    const uint32_t smb = smem_u32(sm);
    const int tid = threadIdx.x;
    const int wid = tid >> 5, L = tid & 31;
    const int ib = (int)gridDim.x - 1 - (int)blockIdx.x;   // heaviest first
    const int h = blockIdx.y, b = blockIdx.z;
    const int r0 = ib << 7;
    const int wr0 = wid << 4;

    const float* qg  = g_qproj + (size_t)b * NSEQ * INNER + h * DH;
    const float* kvg = g_kv + (size_t)b * NSEQ * (2 * DH);

#pragma unroll
    for (int t = 0; t < 16; t++) {
        int idx = tid + (t << 8);
        int r = idx >> 5, c4 = idx & 31;
        float4 v = *(const float4*)&qg[(size_t)(r0 + r) * INNER + (c4 << 2)];
        uint32_t h0, l0, h1, l1;
        split_pair(v.x, v.y, h0, l0);
        split_pair(v.z, v.w, h1, l1);
        uint32_t off = (uint32_t)r * FB_PITCH + (c4 << 3);
        *(uint2*)(sm + off)           = make_uint2(h0, h1);
        *(uint2*)(sm + FB_SIZE + off) = make_uint2(l0, l1);
    }

    const uint32_t aoff = (uint32_t)(wr0 + (L & 15)) * FB_PITCH + ((L >> 4) << 4);
    const uint32_t koff = (uint32_t)(((L >> 4) << 3) + (L & 7)) * FB_PITCH
                          + (((L >> 3) & 1) << 4);
    const uint32_t voff = (uint32_t)((((L >> 3) & 1) << 3) + (L & 7)) * FB_PITCH
                          + ((L >> 4) << 4);

    float sO[16][4];
    float m_i[2], l_i[2];
#pragma unroll
    for (int nj = 0; nj < 16; nj++)
#pragma unroll
        for (int e = 0; e < 4; e++) sO[nj][e] = 0.f;
    m_i[0] = m_i[1] = -INFINITY;
    l_i[0] = l_i[1] = 0.f;

#pragma unroll 1
    for (int jb = 0; jb <= ib; jb++) {
        __syncthreads();
        const int c0 = jb << 7;
#pragma unroll
        for (int t = 0; t < 16; t++) {
            int idx = tid + (t << 8);
            int r = idx >> 5, c4 = idx & 31;
            const float4* row = (const float4*)&kvg[(size_t)(c0 + r) * 256];
            uint32_t off = (uint32_t)r * FB_PITCH + (c4 << 3);
            float4 kv4 = row[c4];
            uint32_t h0, l0, h1, l1;
            split_pair(kv4.x, kv4.y, h0, l0);
            split_pair(kv4.z, kv4.w, h1, l1);
            *(uint2*)(sm + 2 * FB_SIZE + off) = make_uint2(h0, h1);
            *(uint2*)(sm + 3 * FB_SIZE + off) = make_uint2(l0, l1);
            float4 vv4 = row[32 + c4];
            split_pair(vv4.x, vv4.y, h0, l0);
            split_pair(vv4.z, vv4.w, h1, l1);
            *(uint2*)(sm + 4 * FB_SIZE + off) = make_uint2(h0, h1);
            *(uint2*)(sm + 5 * FB_SIZE + off) = make_uint2(l0, l1);
        }
        __syncthreads();

        float s[16][4];
#pragma unroll
        for (int nj = 0; nj < 16; nj++)
#pragma unroll
            for (int e = 0; e < 4; e++) s[nj][e] = 0.f;
#pragma unroll
        for (int ks = 0; ks < 8; ks++) {
            const uint32_t kso = (uint32_t)(ks << 5);
            uint32_t ah[4], al[4];
            ldmat_x4(ah, smb + aoff + kso);
            ldmat_x4(al, smb + FB_SIZE + aoff + kso);
#pragma unroll
            for (int g = 0; g < 2; g++) {
                uint32_t bh[8][2], bl[8][2];
#pragma unroll
                for (int jj = 0; jj < 4; jj++) {
                    int njp = g * 4 + jj;
                    uint32_t kd = smb + 2 * FB_SIZE + koff
                                  + (uint32_t)(njp * 16) * FB_PITCH + kso;
                    uint32_t r4[4];
                    ldmat_x4(r4, kd);
                    bh[2 * jj][0] = r4[0]; bh[2 * jj][1] = r4[1];
                    bh[2 * jj + 1][0] = r4[2]; bh[2 * jj + 1][1] = r4[3];
                    ldmat_x4(r4, kd + FB_SIZE);
                    bl[2 * jj][0] = r4[0]; bl[2 * jj][1] = r4[1];
                    bl[2 * jj + 1][0] = r4[2]; bl[2 * jj + 1][1] = r4[3];
                }
#pragma unroll
                for (int t = 0; t < 8; t++) mma_bf16(s[8 * g + t], ah, bh[t]);
#pragma unroll
                for (int t = 0; t < 8; t++) mma_bf16(s[8 * g + t], ah, bl[t]);
#pragma unroll
                for (int t = 0; t < 8; t++) mma_bf16(s[8 * g + t], al, bh[t]);
            }
        }

        if (jb == ib) {
            int rr = L >> 2, cb = (L & 3) << 1;
#pragma unroll
            for (int nj = 0; nj < 16; nj++) {
                int col = nj * 8 + cb;
                int rA = wr0 + rr, rB = rA + 8;
                if (col     > rA) s[nj][0] = -1e30f;
                if (col + 1 > rA) s[nj][1] = -1e30f;
                if (col     > rB) s[nj][2] = -1e30f;
                if (col + 1 > rB) s[nj][3] = -1e30f;
            }
        }

#pragma unroll
        for (int h2 = 0; h2 < 2; h2++) {
            float mx = -INFINITY;
#pragma unroll
            for (int nj = 0; nj < 16; nj++) {
                mx = fmaxf(mx, s[nj][2 * h2]);
                mx = fmaxf(mx, s[nj][2 * h2 + 1]);
            }
            mx = fmaxf(mx, __shfl_xor_sync(0xffffffffu, mx, 1));
            mx = fmaxf(mx, __shfl_xor_sync(0xffffffffu, mx, 2));
            float mn = fmaxf(m_i[h2], mx);
            float alpha = __expf(m_i[h2] - mn);
            m_i[h2] = mn;
            float sum = 0.f;
#pragma unroll
            for (int nj = 0; nj < 16; nj++) {
                float p0 = __expf(s[nj][2 * h2] - mn);
                float p1 = __expf(s[nj][2 * h2 + 1] - mn);
                s[nj][2 * h2] = p0;
                s[nj][2 * h2 + 1] = p1;
                sum += p0 + p1;
            }
            sum += __shfl_xor_sync(0xffffffffu, sum, 1);
            sum += __shfl_xor_sync(0xffffffffu, sum, 2);
            l_i[h2] = l_i[h2] * alpha + sum;
#pragma unroll
            for (int nj = 0; nj < 16; nj++) {
                sO[nj][2 * h2] *= alpha;
                sO[nj][2 * h2 + 1] *= alpha;
            }
        }

#pragma unroll
        for (int ks = 0; ks < 8; ks++) {
            uint32_t pah[4], pal[4];
            split_pair(s[2 * ks][0], s[2 * ks][1], pah[0], pal[0]);
            split_pair(s[2 * ks][2], s[2 * ks][3], pah[1], pal[1]);
            split_pair(s[2 * ks + 1][0], s[2 * ks + 1][1], pah[2], pal[2]);
            split_pair(s[2 * ks + 1][2], s[2 * ks + 1][3], pah[3], pal[3]);
#pragma unroll
            for (int g = 0; g < 2; g++) {
                uint32_t vh[8][2], vl[8][2];
#pragma unroll
                for (int jj = 0; jj < 4; jj++) {
                    int djp = g * 4 + jj;
                    uint32_t vaddr = smb + 4 * FB_SIZE + voff
                                     + (uint32_t)(ks * 16) * FB_PITCH
                                     + (uint32_t)(djp * 32);
                    uint32_t r4[4];
                    ldmat_x4_t(r4, vaddr);
                    vh[2 * jj][0] = r4[0]; vh[2 * jj][1] = r4[1];
                    vh[2 * jj + 1][0] = r4[2]; vh[2 * jj + 1][1] = r4[3];
                    ldmat_x4_t(r4, vaddr + FB_SIZE);
                    vl[2 * jj][0] = r4[0]; vl[2 * jj][1] = r4[1];
                    vl[2 * jj + 1][0] = r4[2]; vl[2 * jj + 1][1] = r4[3];
                }
#pragma unroll
                for (int t = 0; t < 8; t++) mma_bf16(sO[8 * g + t], pah, vh[t]);
#pragma unroll
                for (int t = 0; t < 8; t++) mma_bf16(sO[8 * g + t], pal, vh[t]);
#pragma unroll
                for (int t = 0; t < 8; t++) mma_bf16(sO[8 * g + t], pah, vl[t]);
            }
        }
    }

    float* og = g_attn + (size_t)b * NSEQ * INNER + h * DH;
    int rowa = r0 + wr0 + (L >> 2);
#pragma unroll
    for (int h2 = 0; h2 < 2; h2++) {
        float inv = 1.f / l_i[h2];
        float* orow = &og[(size_t)(rowa + 8 * h2) * INNER];
#pragma unroll
        for (int nj = 0; nj < 16; nj++) {
            int col = nj * 8 + ((L & 3) << 1);
            *(float2*)&orow[col] =
                make_float2(sO[nj][2 * h2] * inv, sO[nj][2 * h2 + 1] * inv);
        }
    }
}

// ---------------------------------------------------------------------------
extern "C" void kernel_launch(void* const* d_in, const int* in_sizes, int n_in,
                              void* d_out, int out_size)
{
    (void)in_sizes; (void)n_in; (void)out_size;
    const float* x    = (const float*)d_in[0];
    const float* Wq   = (const float*)d_in[1];
    const float* Wkv  = (const float*)d_in[2];
    const float* Wout = (const float*)d_in[3];
    float* out = (float*)d_out;

    void *pq, *pkv, *pattn, *pwt, *pwoutt;
    cudaGetSymbolAddress(&pq, g_qproj);
    cudaGetSymbolAddress(&pkv, g_kv);
    cudaGetSymbolAddress(&pattn, g_attn);
    cudaGetSymbolAddress(&pwt, g_WT);
    cudaGetSymbolAddress(&pwoutt, g_WoutT);

    cudaFuncSetAttribute(gemm_mma,
                         cudaFuncAttributeMaxDynamicSharedMemorySize, GEMM_SMEM);
    cudaFuncSetAttribute(flash_mma,
                         cudaFuncAttributeMaxDynamicSharedMemorySize, FLASH_SMEM);

    const int M = BATCH * NSEQ;  // 4096
    const int NTOT = INNER + 2 * DH;  // 2304
    dim3 tb(32, 8);

    // 0) transpose weights: Wq^T -> g_WT rows [0,2048), Wkv^T -> rows [2048,2304)
    transpose_kernel<<<dim3(INNER / 32, DIM / 32), tb>>>(Wq, (float*)pwt, DIM, INNER);
    transpose_kernel<<<dim3((2 * DH) / 32, DIM / 32), tb>>>(
        Wkv, (float*)pwt + (size_t)INNER * DIM, DIM, 2 * DH);
    transpose_kernel<<<dim3(DIM / 32, INNER / 32), tb>>>(Wout, (float*)pwoutt, INNER, DIM);

    // 1) fused [q | kv] = x @ [Wq | Wkv]   (one 576-CTA launch)
    gemm_mma<<<dim3(NTOT / 128, M / 128), 256, GEMM_SMEM>>>(
        x, (const float*)pwt, (float*)pq, (float*)pkv, M, INNER, 2 * DH);
    // 2) RoPE in place (+ q scaling)
    {
        int tot = BATCH * NSEQ * 17 * 64;
        rope_kernel<<<(tot + 255) / 256, 256>>>();
    }
    // 3) causal flash attention (heaviest-first block order)
    flash_mma<<<dim3(NSEQ / 128, NH, BATCH), 256, FLASH_SMEM>>>();
    // 4) out = attn @ Wout
    gemm_mma<<<dim3(DIM / 128, M / 128), 256, GEMM_SMEM>>>(
        (const float*)pattn, (const float*)pwoutt, out, out, M, DIM, DIM);
}